// round 2
// baseline (speedup 1.0000x reference)
#include <cuda_runtime.h>
#include <cuda_bf16.h>
#include <math.h>
#include <stdint.h>

// Problem constants
#define Lc 4096
#define Ec 256
#define Hc 128
#define Tc 64
#define Dc 12
#define Nc 8191            // 2*L-1
#define NEDGE 8190         // N-1

// ---------------- scratch (device globals; no allocation) ----------------
__device__ float g_xg[Lc * 512];                 // precomputed W_ih@x + b_ih + b_hh   (8 MB)
__device__ float g_hidden[Nc * Hc];              // node hidden states                 (4.2 MB)
__device__ float g_P[NEDGE * 256];               // [hidden[parent], hidden[child]]    (8.4 MB)
__device__ float g_unary[Nc * Tc];
__device__ float g_v2f[Nc * Tc];
__device__ float g_f2p[Nc * Tc];
__device__ float g_f2n[Nc * Tc];
__device__ float g_edge[(size_t)NEDGE * 4096];   // edge factors                       (134 MB)

// ---------------- Stage A: embedding + input projection -------------------
// xg[t][j] = b_ih[j] + b_hh[j] + sum_e W_ih[j,e] * emb[tokens[t], e]
// 4 tokens per block, 128 threads, each thread computes 4 gate rows.
__global__ void embed_gemm_kernel(const int* __restrict__ tokens,
                                  const float* __restrict__ emb,
                                  const float* __restrict__ W_ih,
                                  const float* __restrict__ b_ih,
                                  const float* __restrict__ b_hh) {
    __shared__ float es[4][256];
    int t0 = blockIdx.x * 4;
    int tid = threadIdx.x;
    for (int i = tid; i < 4 * 256; i += 128) {
        int tl = i >> 8, k = i & 255;
        es[tl][k] = emb[(size_t)tokens[t0 + tl] * Ec + k];
    }
    __syncthreads();
    for (int r = 0; r < 4; r++) {
        int j = tid + 128 * r;
        float a0 = 0.f, a1 = 0.f, a2 = 0.f, a3 = 0.f;
        const float4* w4 = (const float4*)(W_ih + (size_t)j * 256);
        const float4* e0 = (const float4*)es[0];
        const float4* e1 = (const float4*)es[1];
        const float4* e2 = (const float4*)es[2];
        const float4* e3 = (const float4*)es[3];
#pragma unroll 8
        for (int k = 0; k < 64; k++) {
            float4 w = __ldg(&w4[k]);
            float4 v;
            v = e0[k]; a0 += w.x * v.x + w.y * v.y + w.z * v.z + w.w * v.w;
            v = e1[k]; a1 += w.x * v.x + w.y * v.y + w.z * v.z + w.w * v.w;
            v = e2[k]; a2 += w.x * v.x + w.y * v.y + w.z * v.z + w.w * v.w;
            v = e3[k]; a3 += w.x * v.x + w.y * v.y + w.z * v.z + w.w * v.w;
        }
        float bias = b_ih[j] + b_hh[j];
        g_xg[(size_t)(t0 + 0) * 512 + j] = a0 + bias;
        g_xg[(size_t)(t0 + 1) * 512 + j] = a1 + bias;
        g_xg[(size_t)(t0 + 2) * 512 + j] = a2 + bias;
        g_xg[(size_t)(t0 + 3) * 512 + j] = a3 + bias;
    }
}

// ---------------- Stage B: sequential LSTM (single CTA) -------------------
__device__ __forceinline__ float sigf(float x) { return 1.0f / (1.0f + expf(-x)); }

__global__ void __launch_bounds__(512, 1) lstm_kernel(const float* __restrict__ W_hh) {
    __shared__ float h_s[128];
    __shared__ float c_s[128];
    __shared__ float g_s[512];
    int tid = threadIdx.x;
    if (tid < 128) { h_s[tid] = 0.f; c_s[tid] = 0.f; }
    __syncthreads();
    const float4* w4 = (const float4*)(W_hh + (size_t)tid * 128);
    float* leaf = g_hidden + (size_t)(Lc - 1) * Hc;
    for (int t = 0; t < Lc; t++) {
        float acc = g_xg[(size_t)t * 512 + tid];
        const float4* h4 = (const float4*)h_s;
#pragma unroll
        for (int k = 0; k < 32; k++) {
            float4 w = __ldg(&w4[k]);
            float4 hv = h4[k];
            acc += w.x * hv.x + w.y * hv.y + w.z * hv.z + w.w * hv.w;
        }
        g_s[tid] = acc;
        __syncthreads();
        if (tid < 128) {
            float ig = sigf(g_s[tid]);
            float fg = sigf(g_s[tid + 128]);
            float gg = tanhf(g_s[tid + 256]);
            float og = sigf(g_s[tid + 384]);
            float c = fg * c_s[tid] + ig * gg;
            c_s[tid] = c;
            float h = og * tanhf(c);
            h_s[tid] = h;
            leaf[(size_t)t * Hc + tid] = h;
        }
        __syncthreads();
    }
}

// ---------------- Stage C: bottom-up pair fusion --------------------------
// hidden[i] = W_p2h @ [hidden[2i+1]; hidden[2i+2]] + b_p2h
__global__ void p2h_kernel(const float* __restrict__ Wp, const float* __restrict__ bp,
                           int base) {
    int node = base + blockIdx.x;
    __shared__ float pair[256];
    int tid = threadIdx.x;  // 128
    pair[tid] = g_hidden[(size_t)(2 * node + 1) * Hc + tid];
    pair[tid + 128] = g_hidden[(size_t)(2 * node + 2) * Hc + tid];
    __syncthreads();
    float acc = bp[tid];
    const float4* w = (const float4*)(Wp + (size_t)tid * 256);
    const float4* p4 = (const float4*)pair;
#pragma unroll 8
    for (int k = 0; k < 64; k++) {
        float4 wv = __ldg(&w[k]);
        float4 pv = p4[k];
        acc += wv.x * pv.x + wv.y * pv.y + wv.z * pv.z + wv.w * pv.w;
    }
    g_hidden[(size_t)node * Hc + tid] = acc;
}

// ---------------- Stage D: unary factors (+ v2f init, f2n root zero) ------
__global__ void unary_kernel(const float* __restrict__ W_uni, const float* __restrict__ b_uni) {
    int node = blockIdx.x;
    int t = threadIdx.x;  // 64
    __shared__ float hs[128];
    hs[t] = g_hidden[(size_t)node * Hc + t];
    hs[t + 64] = g_hidden[(size_t)node * Hc + 64 + t];
    __syncthreads();
    float acc = b_uni[t];
    const float4* w = (const float4*)(W_uni + (size_t)t * 128);
    const float4* h4 = (const float4*)hs;
#pragma unroll
    for (int k = 0; k < 32; k++) {
        float4 wv = __ldg(&w[k]);
        float4 hv = h4[k];
        acc += wv.x * hv.x + wv.y * hv.y + wv.z * hv.z + wv.w * hv.w;
    }
    g_unary[(size_t)node * Tc + t] = acc;
    g_v2f[(size_t)node * Tc + t] = acc;
    if (node == 0) g_f2n[t] = 0.f;  // root receives no downward message
}

// ---------------- Stage E1: build pair matrix P ---------------------------
__global__ void pbuild_kernel() {
    int e = blockIdx.x;           // edge index = child-1, 0..8189
    int child = e + 1;
    int parent = e >> 1;          // (child-1)/2
    int tid = threadIdx.x;        // 256
    g_P[(size_t)e * 256 + tid] =
        (tid < 128) ? g_hidden[(size_t)parent * Hc + tid]
                    : g_hidden[(size_t)child * Hc + (tid - 128)];
}

// ---------------- Stage E2: edge factor GEMM ------------------------------
// C[8190][4096] = P[8190][256] @ W_edge^T + b_edge   (W_edge row-major [4096][256])
__global__ void __launch_bounds__(256) edge_gemm_kernel(const float* __restrict__ W,
                                                        const float* __restrict__ bias) {
    const int M = NEDGE, Ndim = 4096, K = 256;
    const int BM = 64, BN = 64, BK = 32;
    __shared__ float As[BK][BM];
    __shared__ float Bs[BK][BN];
    int m0 = blockIdx.y * BM;
    int n0 = blockIdx.x * BN;
    int tid = threadIdx.x;
    int tx = tid & 15, ty = tid >> 4;
    float acc[4][4] = {};
    for (int k0 = 0; k0 < K; k0 += BK) {
#pragma unroll 4
        for (int idx = tid; idx < BM * BK; idx += 256) {
            int m = idx / BK, k = idx % BK;
            As[k][m] = (m0 + m < M) ? g_P[(size_t)(m0 + m) * K + k0 + k] : 0.f;
        }
#pragma unroll 4
        for (int idx = tid; idx < BN * BK; idx += 256) {
            int n = idx / BK, k = idx % BK;
            Bs[k][n] = W[(size_t)(n0 + n) * K + k0 + k];
        }
        __syncthreads();
#pragma unroll
        for (int kk = 0; kk < BK; kk++) {
            float a[4], b[4];
#pragma unroll
            for (int i = 0; i < 4; i++) a[i] = As[kk][ty * 4 + i];
#pragma unroll
            for (int j = 0; j < 4; j++) b[j] = Bs[kk][tx * 4 + j];
#pragma unroll
            for (int i = 0; i < 4; i++)
#pragma unroll
                for (int j = 0; j < 4; j++) acc[i][j] += a[i] * b[j];
        }
        __syncthreads();
    }
#pragma unroll
    for (int i = 0; i < 4; i++) {
        int m = m0 + ty * 4 + i;
        if (m < M) {
#pragma unroll
            for (int j = 0; j < 4; j++) {
                int n = n0 + tx * 4 + j;
                g_edge[(size_t)m * Ndim + n] = acc[i][j] + bias[n];
            }
        }
    }
}

// ---------------- Stage F: upward pass (one level) ------------------------
__global__ void up_kernel(int base, int leafLevel, int hasParent) {
    int idx = base + blockIdx.x;
    int t = threadIdx.x;  // 64
    __shared__ float v[64];
    float val = g_v2f[(size_t)idx * Tc + t];
    if (!leafLevel) {
        val += g_f2p[(size_t)(2 * idx + 1) * Tc + t] + g_f2p[(size_t)(2 * idx + 2) * Tc + t];
        g_v2f[(size_t)idx * Tc + t] = val;
    }
    v[t] = val;
    __syncthreads();
    if (hasParent) {
        const float4* row = (const float4*)(g_edge + (size_t)(idx - 1) * 4096 + t * 64);
        float r[64];
#pragma unroll
        for (int c = 0; c < 16; c++) {
            float4 x = __ldg(row + c);
            r[4 * c] = x.x; r[4 * c + 1] = x.y; r[4 * c + 2] = x.z; r[4 * c + 3] = x.w;
        }
        float m = -3.4e38f;
#pragma unroll
        for (int c = 0; c < 64; c++) { r[c] += v[c]; m = fmaxf(m, r[c]); }
        float s = 0.f;
#pragma unroll
        for (int c = 0; c < 64; c++) s += expf(r[c] - m);
        g_f2p[(size_t)idx * Tc + t] = m + logf(s);
    }
}

// ---------------- Stage G: downward pass (one level) ----------------------
__global__ void down_kernel(int base) {
    int idx = base + blockIdx.x;
    int t = threadIdx.x;  // 64
    int par = (idx - 1) >> 1;
    int sib = (idx & 1) ? idx + 1 : idx - 1;
    __shared__ float p[64];
    p[t] = g_unary[(size_t)par * Tc + t] + g_f2n[(size_t)par * Tc + t]
         + g_f2p[(size_t)sib * Tc + t];
    __syncthreads();
    const float* e0 = g_edge + (size_t)(idx - 1) * 4096 + t;
    float r[64];
    float m = -3.4e38f;
#pragma unroll
    for (int tp = 0; tp < 64; tp++) {
        r[tp] = e0[(size_t)tp * 64] + p[tp];
        m = fmaxf(m, r[tp]);
    }
    float s = 0.f;
#pragma unroll
    for (int tp = 0; tp < 64; tp++) s += expf(r[tp] - m);
    g_f2n[(size_t)idx * Tc + t] = m + logf(s);
}

// ---------------- Stage H: beliefs + postorder scatter --------------------
__global__ void out_kernel(float* __restrict__ out) {
    int node = blockIdx.x;
    int t = threadIdx.x;  // 64
    int x = node + 1;
    int d = 31 - __clz(x);
    int start = 0, size = Nc;
    for (int b = d - 1; b >= 0; b--) {
        int half = (size - 1) >> 1;
        if ((x >> b) & 1) start += half;
        size = half;
    }
    int post = start + size - 1;
    out[(size_t)post * Tc + t] = g_v2f[(size_t)node * Tc + t] + g_f2n[(size_t)node * Tc + t];
}

// ---------------- launch ---------------------------------------------------
extern "C" void kernel_launch(void* const* d_in, const int* in_sizes, int n_in,
                              void* d_out, int out_size) {
    const int*   tokens = (const int*)d_in[0];
    const float* emb    = (const float*)d_in[1];
    const float* W_ih   = (const float*)d_in[2];
    const float* W_hh   = (const float*)d_in[3];
    const float* b_ih   = (const float*)d_in[4];
    const float* b_hh   = (const float*)d_in[5];
    const float* W_p2h  = (const float*)d_in[6];
    const float* b_p2h  = (const float*)d_in[7];
    const float* W_uni  = (const float*)d_in[8];
    const float* b_uni  = (const float*)d_in[9];
    const float* W_edge = (const float*)d_in[10];
    const float* b_edge = (const float*)d_in[11];
    float* out = (float*)d_out;

    // A: embedding + input projection
    embed_gemm_kernel<<<Lc / 4, 128>>>(tokens, emb, W_ih, b_ih, b_hh);
    // B: sequential LSTM
    lstm_kernel<<<1, 512>>>(W_hh);
    // C: bottom-up fusion, levels D-1 .. 0
    for (int d = Dc - 1; d >= 0; d--) {
        int base = (1 << d) - 1;
        p2h_kernel<<<(1 << d), 128>>>(W_p2h, b_p2h, base);
    }
    // D: unary factors (+ v2f init, f2n root zero)
    unary_kernel<<<Nc, 64>>>(W_uni, b_uni);
    // E: edge factor GEMM
    pbuild_kernel<<<NEDGE, 256>>>();
    {
        dim3 grid(4096 / 64, (NEDGE + 63) / 64);
        edge_gemm_kernel<<<grid, 256>>>(W_edge, b_edge);
    }
    // F: upward pass, levels D .. 0
    for (int d = Dc; d >= 0; d--) {
        int base = (1 << d) - 1;
        up_kernel<<<(1 << d), 64>>>(base, d == Dc ? 1 : 0, d > 0 ? 1 : 0);
    }
    // G: downward pass, levels 1 .. D
    for (int d = 1; d <= Dc; d++) {
        int base = (1 << d) - 1;
        down_kernel<<<(1 << d), 64>>>(base);
    }
    // H: beliefs in postorder
    out_kernel<<<Nc, 64>>>(out);
}

// round 3
// speedup vs baseline: 5.9706x; 5.9706x over previous
#include <cuda_runtime.h>
#include <cuda_bf16.h>
#include <math.h>
#include <stdint.h>

// Problem constants
#define Lc 4096
#define Ec 256
#define Hc 128
#define Tc 64
#define Dc 12
#define Nc 8191            // 2*L-1
#define NEDGE 8190         // N-1

// ---------------- scratch (device globals; no allocation) ----------------
__device__ float g_xg[Lc * 512];                 // W_ih@x + b_ih + b_hh   (8 MB)
__device__ float g_hidden[Nc * Hc];              // node hidden states
__device__ float g_unary[Nc * Tc];
__device__ float g_v2f[Nc * Tc];
__device__ float g_f2p[Nc * Tc];
__device__ float g_f2n[Nc * Tc];
__device__ float g_edge[(size_t)NEDGE * 4096];   // edge factors (134 MB)

// ---------------- Stage A: embedding + input projection -------------------
__global__ void embed_gemm_kernel(const int* __restrict__ tokens,
                                  const float* __restrict__ emb,
                                  const float* __restrict__ W_ih,
                                  const float* __restrict__ b_ih,
                                  const float* __restrict__ b_hh) {
    __shared__ float es[4][256];
    int t0 = blockIdx.x * 4;
    int tid = threadIdx.x;
    for (int i = tid; i < 4 * 256; i += 128) {
        int tl = i >> 8, k = i & 255;
        es[tl][k] = emb[(size_t)tokens[t0 + tl] * Ec + k];
    }
    __syncthreads();
    for (int r = 0; r < 4; r++) {
        int j = tid + 128 * r;
        float a0 = 0.f, a1 = 0.f, a2 = 0.f, a3 = 0.f;
        const float4* w4 = (const float4*)(W_ih + (size_t)j * 256);
        const float4* e0 = (const float4*)es[0];
        const float4* e1 = (const float4*)es[1];
        const float4* e2 = (const float4*)es[2];
        const float4* e3 = (const float4*)es[3];
#pragma unroll 8
        for (int k = 0; k < 64; k++) {
            float4 w = __ldg(&w4[k]);
            float4 v;
            v = e0[k]; a0 += w.x * v.x + w.y * v.y + w.z * v.z + w.w * v.w;
            v = e1[k]; a1 += w.x * v.x + w.y * v.y + w.z * v.z + w.w * v.w;
            v = e2[k]; a2 += w.x * v.x + w.y * v.y + w.z * v.z + w.w * v.w;
            v = e3[k]; a3 += w.x * v.x + w.y * v.y + w.z * v.z + w.w * v.w;
        }
        float bias = b_ih[j] + b_hh[j];
        g_xg[(size_t)(t0 + 0) * 512 + j] = a0 + bias;
        g_xg[(size_t)(t0 + 1) * 512 + j] = a1 + bias;
        g_xg[(size_t)(t0 + 2) * 512 + j] = a2 + bias;
        g_xg[(size_t)(t0 + 3) * 512 + j] = a3 + bias;
    }
}

// ---------------- Stage B: sequential LSTM (single CTA, on-chip weights) --
__device__ __forceinline__ float sigf(float x) { return 1.0f / (1.0f + expf(-x)); }

// dynamic smem layout (floats):
//   [0, 32768)        Wsm: float2[32][512]   (k=64..127 of each row, transposed)
//   [32768, 33280)    g_s[512]
//   [33280, 33408)    h_s[128]
//   [33408, 33536)    c_s[128]
#define LSTM_SMEM_BYTES ((32768 + 512 + 128 + 128) * 4)

__global__ void __launch_bounds__(512, 1) lstm_kernel(const float* __restrict__ W_hh) {
    extern __shared__ float sm[];
    float2* Wsm = (float2*)sm;            // [kk*512 + row]
    float*  g_s = sm + 32768;
    float*  h_s = sm + 32768 + 512;
    float*  c_s = sm + 32768 + 512 + 128;

    int tid = threadIdx.x;

    // preload register half (k = 0..63)
    float4 wr[16];
    const float4* wrow = (const float4*)(W_hh + (size_t)tid * 128);
#pragma unroll
    for (int i = 0; i < 16; i++) wr[i] = wrow[i];

    // stage smem half (k = 64..127), transposed: Wsm[kk][row]
#pragma unroll
    for (int kk = 0; kk < 32; kk++) {
        Wsm[kk * 512 + tid] = *(const float2*)(W_hh + (size_t)tid * 128 + 64 + 2 * kk);
    }
    if (tid < 128) { h_s[tid] = 0.f; c_s[tid] = 0.f; }
    __syncthreads();

    float* leaf = g_hidden + (size_t)(Lc - 1) * Hc;
    float xg = g_xg[tid];

    for (int t = 0; t < Lc; t++) {
        float acc = xg;
        // prefetch next step's input-gate preactivation early
        float xg_n = 0.f;
        if (t + 1 < Lc) xg_n = g_xg[(size_t)(t + 1) * 512 + tid];

        // register half (h broadcast from smem)
        const float4* h4 = (const float4*)h_s;
        float acc2 = 0.f;
#pragma unroll
        for (int i = 0; i < 16; i++) {
            float4 hv = h4[i];
            acc  += wr[i].x * hv.x + wr[i].y * hv.y;
            acc2 += wr[i].z * hv.z + wr[i].w * hv.w;
        }
        // smem half (conflict-free: lanes read consecutive rows)
        const float2* h2 = (const float2*)(h_s + 64);
#pragma unroll
        for (int kk = 0; kk < 32; kk++) {
            float2 wv = Wsm[kk * 512 + tid];
            float2 hv = h2[kk];
            acc  += wv.x * hv.x;
            acc2 += wv.y * hv.y;
        }
        g_s[tid] = acc + acc2;
        __syncthreads();
        if (tid < 128) {
            float ig = sigf(g_s[tid]);
            float fg = sigf(g_s[tid + 128]);
            float gg = tanhf(g_s[tid + 256]);
            float og = sigf(g_s[tid + 384]);
            float c = fg * c_s[tid] + ig * gg;
            c_s[tid] = c;
            float h = og * tanhf(c);
            h_s[tid] = h;
            leaf[(size_t)t * Hc + tid] = h;
        }
        __syncthreads();
        xg = xg_n;
    }
}

// ---------------- Stage C: bottom-up pair fusion (4 nodes/block) ----------
__global__ void p2h_kernel(const float* __restrict__ Wp, const float* __restrict__ bp,
                           int base, int count) {
    int n0 = base + blockIdx.x * 4;
    __shared__ float pair[4][256];
    int tid = threadIdx.x;  // 128
#pragma unroll
    for (int b = 0; b < 4; b++) {
        int node = n0 + b;
        if (node < base + count) {
            pair[b][tid]       = g_hidden[(size_t)(2 * node + 1) * Hc + tid];
            pair[b][tid + 128] = g_hidden[(size_t)(2 * node + 2) * Hc + tid];
        } else {
            pair[b][tid] = 0.f; pair[b][tid + 128] = 0.f;
        }
    }
    __syncthreads();
    float a0 = 0.f, a1 = 0.f, a2 = 0.f, a3 = 0.f;
    const float4* w = (const float4*)(Wp + (size_t)tid * 256);
    const float4* p0 = (const float4*)pair[0];
    const float4* p1 = (const float4*)pair[1];
    const float4* p2 = (const float4*)pair[2];
    const float4* p3 = (const float4*)pair[3];
#pragma unroll 8
    for (int k = 0; k < 64; k++) {
        float4 wv = __ldg(&w[k]);
        float4 v;
        v = p0[k]; a0 += wv.x * v.x + wv.y * v.y + wv.z * v.z + wv.w * v.w;
        v = p1[k]; a1 += wv.x * v.x + wv.y * v.y + wv.z * v.z + wv.w * v.w;
        v = p2[k]; a2 += wv.x * v.x + wv.y * v.y + wv.z * v.z + wv.w * v.w;
        v = p3[k]; a3 += wv.x * v.x + wv.y * v.y + wv.z * v.z + wv.w * v.w;
    }
    float bias = bp[tid];
    if (n0 + 0 < base + count) g_hidden[(size_t)(n0 + 0) * Hc + tid] = a0 + bias;
    if (n0 + 1 < base + count) g_hidden[(size_t)(n0 + 1) * Hc + tid] = a1 + bias;
    if (n0 + 2 < base + count) g_hidden[(size_t)(n0 + 2) * Hc + tid] = a2 + bias;
    if (n0 + 3 < base + count) g_hidden[(size_t)(n0 + 3) * Hc + tid] = a3 + bias;
}

// ---------------- Stage D: unary factors (+ v2f init, f2n root zero) ------
__global__ void unary_kernel(const float* __restrict__ W_uni, const float* __restrict__ b_uni) {
    int node = blockIdx.x;
    int t = threadIdx.x;  // 64
    __shared__ float hs[128];
    hs[t] = g_hidden[(size_t)node * Hc + t];
    hs[t + 64] = g_hidden[(size_t)node * Hc + 64 + t];
    __syncthreads();
    float acc = b_uni[t];
    const float4* w = (const float4*)(W_uni + (size_t)t * 128);
    const float4* h4 = (const float4*)hs;
#pragma unroll
    for (int k = 0; k < 32; k++) {
        float4 wv = __ldg(&w[k]);
        float4 hv = h4[k];
        acc += wv.x * hv.x + wv.y * hv.y + wv.z * hv.z + wv.w * hv.w;
    }
    g_unary[(size_t)node * Tc + t] = acc;
    g_v2f[(size_t)node * Tc + t] = acc;
    if (node == 0) g_f2n[t] = 0.f;
}

// ---------------- Stage E: edge factor GEMM -------------------------------
// C[8190][4096] = P @ W_edge^T + b_edge; P rows built on the fly from g_hidden.
// 128x128x16 tiles, 256 threads, 8x8 microtile (split 4+4 for conflict-free LDS).
__global__ void __launch_bounds__(256) edge_gemm_kernel(const float* __restrict__ W,
                                                        const float* __restrict__ bias) {
    const int M = NEDGE;
    __shared__ float As[16][132];
    __shared__ float Bs[16][132];
    int m0 = blockIdx.y * 128;
    int n0 = blockIdx.x * 128;
    int tid = threadIdx.x;
    int tx = tid & 15, ty = tid >> 4;
    float acc[8][8] = {};

    for (int k0 = 0; k0 < 256; k0 += 16) {
        // A tile: 128 edges x 16 k  (512 float4 loads, 2/thread)
#pragma unroll
        for (int i = 0; i < 2; i++) {
            int idx = tid + i * 256;
            int m = idx & 127, k4 = idx >> 7;   // k4 0..3
            int e = m0 + m;
            float4 v = make_float4(0.f, 0.f, 0.f, 0.f);
            if (e < M) {
                int kk = k0 + k4 * 4;
                int child = e + 1, parent = e >> 1;
                const float* src = (kk < 128)
                    ? g_hidden + (size_t)parent * Hc + kk
                    : g_hidden + (size_t)child * Hc + (kk - 128);
                v = *(const float4*)src;
            }
            As[k4 * 4 + 0][m] = v.x; As[k4 * 4 + 1][m] = v.y;
            As[k4 * 4 + 2][m] = v.z; As[k4 * 4 + 3][m] = v.w;
        }
        // B tile: 128 n-rows x 16 k
#pragma unroll
        for (int i = 0; i < 2; i++) {
            int idx = tid + i * 256;
            int n = idx & 127, k4 = idx >> 7;
            float4 v = __ldg((const float4*)(W + (size_t)(n0 + n) * 256 + k0 + k4 * 4));
            Bs[k4 * 4 + 0][n] = v.x; Bs[k4 * 4 + 1][n] = v.y;
            Bs[k4 * 4 + 2][n] = v.z; Bs[k4 * 4 + 3][n] = v.w;
        }
        __syncthreads();
#pragma unroll
        for (int kk = 0; kk < 16; kk++) {
            float4 aA = *(const float4*)&As[kk][ty * 4];
            float4 aB = *(const float4*)&As[kk][64 + ty * 4];
            float4 bA = *(const float4*)&Bs[kk][tx * 4];
            float4 bB = *(const float4*)&Bs[kk][64 + tx * 4];
            float a[8] = {aA.x, aA.y, aA.z, aA.w, aB.x, aB.y, aB.z, aB.w};
            float b[8] = {bA.x, bA.y, bA.z, bA.w, bB.x, bB.y, bB.z, bB.w};
#pragma unroll
            for (int i = 0; i < 8; i++)
#pragma unroll
                for (int j = 0; j < 8; j++) acc[i][j] += a[i] * b[j];
        }
        __syncthreads();
    }
    // store
#pragma unroll
    for (int hi = 0; hi < 2; hi++) {
#pragma unroll
        for (int i = 0; i < 4; i++) {
            int m = m0 + hi * 64 + ty * 4 + i;
            if (m < M) {
#pragma unroll
                for (int hj = 0; hj < 2; hj++) {
#pragma unroll
                    for (int j = 0; j < 4; j++) {
                        int n = n0 + hj * 64 + tx * 4 + j;
                        g_edge[(size_t)m * 4096 + n] = acc[hi * 4 + i][hj * 4 + j] + bias[n];
                    }
                }
            }
        }
    }
}

// ---------------- Stage F: upward pass (one level) ------------------------
__global__ void up_kernel(int base, int leafLevel, int hasParent) {
    int idx = base + blockIdx.x;
    int t = threadIdx.x;  // 64
    __shared__ float v[64];
    float val = g_v2f[(size_t)idx * Tc + t];
    if (!leafLevel) {
        val += g_f2p[(size_t)(2 * idx + 1) * Tc + t] + g_f2p[(size_t)(2 * idx + 2) * Tc + t];
        g_v2f[(size_t)idx * Tc + t] = val;
    }
    v[t] = val;
    __syncthreads();
    if (hasParent) {
        const float4* row = (const float4*)(g_edge + (size_t)(idx - 1) * 4096 + t * 64);
        float r[64];
#pragma unroll
        for (int c = 0; c < 16; c++) {
            float4 x = __ldg(row + c);
            r[4 * c] = x.x; r[4 * c + 1] = x.y; r[4 * c + 2] = x.z; r[4 * c + 3] = x.w;
        }
        float m = -3.4e38f;
#pragma unroll
        for (int c = 0; c < 64; c++) { r[c] += v[c]; m = fmaxf(m, r[c]); }
        float s = 0.f;
#pragma unroll
        for (int c = 0; c < 64; c++) s += expf(r[c] - m);
        g_f2p[(size_t)idx * Tc + t] = m + logf(s);
    }
}

// ---------------- Stage G: downward pass (one level) ----------------------
__global__ void down_kernel(int base) {
    int idx = base + blockIdx.x;
    int t = threadIdx.x;  // 64
    int par = (idx - 1) >> 1;
    int sib = (idx & 1) ? idx + 1 : idx - 1;
    __shared__ float p[64];
    p[t] = g_unary[(size_t)par * Tc + t] + g_f2n[(size_t)par * Tc + t]
         + g_f2p[(size_t)sib * Tc + t];
    __syncthreads();
    const float* e0 = g_edge + (size_t)(idx - 1) * 4096 + t;
    float r[64];
    float m = -3.4e38f;
#pragma unroll
    for (int tp = 0; tp < 64; tp++) {
        r[tp] = e0[(size_t)tp * 64] + p[tp];
        m = fmaxf(m, r[tp]);
    }
    float s = 0.f;
#pragma unroll
    for (int tp = 0; tp < 64; tp++) s += expf(r[tp] - m);
    g_f2n[(size_t)idx * Tc + t] = m + logf(s);
}

// ---------------- Stage H: beliefs + postorder scatter --------------------
__global__ void out_kernel(float* __restrict__ out) {
    int node = blockIdx.x;
    int t = threadIdx.x;  // 64
    int x = node + 1;
    int d = 31 - __clz(x);
    int start = 0, size = Nc;
    for (int b = d - 1; b >= 0; b--) {
        int half = (size - 1) >> 1;
        if ((x >> b) & 1) start += half;
        size = half;
    }
    int post = start + size - 1;
    out[(size_t)post * Tc + t] = g_v2f[(size_t)node * Tc + t] + g_f2n[(size_t)node * Tc + t];
}

// ---------------- launch ---------------------------------------------------
extern "C" void kernel_launch(void* const* d_in, const int* in_sizes, int n_in,
                              void* d_out, int out_size) {
    const int*   tokens = (const int*)d_in[0];
    const float* emb    = (const float*)d_in[1];
    const float* W_ih   = (const float*)d_in[2];
    const float* W_hh   = (const float*)d_in[3];
    const float* b_ih   = (const float*)d_in[4];
    const float* b_hh   = (const float*)d_in[5];
    const float* W_p2h  = (const float*)d_in[6];
    const float* b_p2h  = (const float*)d_in[7];
    const float* W_uni  = (const float*)d_in[8];
    const float* b_uni  = (const float*)d_in[9];
    const float* W_edge = (const float*)d_in[10];
    const float* b_edge = (const float*)d_in[11];
    float* out = (float*)d_out;

    static int smem_set = 0;
    if (!smem_set) {
        cudaFuncSetAttribute(lstm_kernel, cudaFuncAttributeMaxDynamicSharedMemorySize,
                             LSTM_SMEM_BYTES);
        smem_set = 1;
    }

    // A: embedding + input projection
    embed_gemm_kernel<<<Lc / 4, 128>>>(tokens, emb, W_ih, b_ih, b_hh);
    // B: sequential LSTM (weights fully on-chip)
    lstm_kernel<<<1, 512, LSTM_SMEM_BYTES>>>(W_hh);
    // C: bottom-up fusion, levels D-1 .. 0
    for (int d = Dc - 1; d >= 0; d--) {
        int base = (1 << d) - 1;
        int count = 1 << d;
        p2h_kernel<<<(count + 3) / 4, 128>>>(W_p2h, b_p2h, base, count);
    }
    // D: unary factors
    unary_kernel<<<Nc, 64>>>(W_uni, b_uni);
    // E: edge factor GEMM (pbuild folded into A-tile load)
    {
        dim3 grid(4096 / 128, (NEDGE + 127) / 128);
        edge_gemm_kernel<<<grid, 256>>>(W_edge, b_edge);
    }
    // F: upward pass, levels D .. 0
    for (int d = Dc; d >= 0; d--) {
        int base = (1 << d) - 1;
        up_kernel<<<(1 << d), 64>>>(base, d == Dc ? 1 : 0, d > 0 ? 1 : 0);
    }
    // G: downward pass, levels 1 .. D
    for (int d = 1; d <= Dc; d++) {
        int base = (1 << d) - 1;
        down_kernel<<<(1 << d), 64>>>(base);
    }
    // H: beliefs in postorder
    out_kernel<<<Nc, 64>>>(out);
}

// round 4
// speedup vs baseline: 7.8431x; 1.3136x over previous
#include <cuda_runtime.h>
#include <cuda_bf16.h>
#include <math.h>
#include <stdint.h>

// Problem constants
#define Lc 4096
#define Ec 256
#define Hc 128
#define Tc 64
#define Dc 12
#define Nc 8191            // 2*L-1
#define NEDGE 8190         // N-1

typedef unsigned long long ull;

// ---------------- packed f32x2 helpers ------------------------------------
__device__ __forceinline__ void fma2(ull& d, ull a, ull b) {
    asm("fma.rn.f32x2 %0, %1, %2, %0;" : "+l"(d) : "l"(a), "l"(b));
}
__device__ __forceinline__ ull splat2(float a) {
    ull r; asm("mov.b64 %0, {%1, %1};" : "=l"(r) : "f"(a)); return r;
}
__device__ __forceinline__ float2 unpk(ull v) {
    float2 r; asm("mov.b64 {%0, %1}, %2;" : "=f"(r.x), "=f"(r.y) : "l"(v)); return r;
}

// ---------------- fast activations ----------------------------------------
__device__ __forceinline__ float fast_sig(float x) {
    float t;
    asm("ex2.approx.f32 %0, %1;" : "=f"(t) : "f"(-1.4426950408889634f * x));
    float r;
    asm("rcp.approx.f32 %0, %1;" : "=f"(r) : "f"(1.0f + t));
    return r;
}
__device__ __forceinline__ float fast_tanh(float x) {
    float r; asm("tanh.approx.f32 %0, %1;" : "=f"(r) : "f"(x)); return r;
}

// ---------------- scratch (device globals; no allocation) ----------------
__device__ float g_xg[Lc * 512];                 // W_ih@x + b_ih + b_hh   (8 MB)
__device__ float g_hidden[Nc * Hc];              // node hidden states
__device__ float g_unary[Nc * Tc];
__device__ float g_v2f[Nc * Tc];
__device__ float g_f2p[Nc * Tc];
__device__ float g_f2n[Nc * Tc];
__device__ float g_edge[(size_t)NEDGE * 4096];   // edge factors (134 MB)

// ---------------- Stage A: embedding + input projection -------------------
__global__ void embed_gemm_kernel(const int* __restrict__ tokens,
                                  const float* __restrict__ emb,
                                  const float* __restrict__ W_ih,
                                  const float* __restrict__ b_ih,
                                  const float* __restrict__ b_hh) {
    __shared__ float es[4][256];
    int t0 = blockIdx.x * 4;
    int tid = threadIdx.x;
    for (int i = tid; i < 4 * 256; i += 128) {
        int tl = i >> 8, k = i & 255;
        es[tl][k] = emb[(size_t)tokens[t0 + tl] * Ec + k];
    }
    __syncthreads();
    for (int r = 0; r < 4; r++) {
        int j = tid + 128 * r;
        float a0 = 0.f, a1 = 0.f, a2 = 0.f, a3 = 0.f;
        const float4* w4 = (const float4*)(W_ih + (size_t)j * 256);
        const float4* e0 = (const float4*)es[0];
        const float4* e1 = (const float4*)es[1];
        const float4* e2 = (const float4*)es[2];
        const float4* e3 = (const float4*)es[3];
#pragma unroll 8
        for (int k = 0; k < 64; k++) {
            float4 w = __ldg(&w4[k]);
            float4 v;
            v = e0[k]; a0 += w.x * v.x + w.y * v.y + w.z * v.z + w.w * v.w;
            v = e1[k]; a1 += w.x * v.x + w.y * v.y + w.z * v.z + w.w * v.w;
            v = e2[k]; a2 += w.x * v.x + w.y * v.y + w.z * v.z + w.w * v.w;
            v = e3[k]; a3 += w.x * v.x + w.y * v.y + w.z * v.z + w.w * v.w;
        }
        float bias = b_ih[j] + b_hh[j];
        g_xg[(size_t)(t0 + 0) * 512 + j] = a0 + bias;
        g_xg[(size_t)(t0 + 1) * 512 + j] = a1 + bias;
        g_xg[(size_t)(t0 + 2) * 512 + j] = a2 + bias;
        g_xg[(size_t)(t0 + 3) * 512 + j] = a3 + bias;
    }
}

// ---------------- Stage B: sequential LSTM (single CTA) -------------------
// Weight split: cols 0..95 in registers (48 ull), cols 96..127 in smem
// (transposed, ull Wsm[kk][row], kk=0..15). f32x2 packed FMA throughout.
// dynamic smem (bytes):
//   [0, 65536)          Wsm: ull[16][512]
//   [65536, 67584)      g_s[512] floats
//   [67584, 68096)      h_s[128]
//   [68096, 68608)      c_s[128]
#define LSTM_SMEM_BYTES (65536 + (512 + 128 + 128) * 4)

__global__ void __launch_bounds__(512, 1) lstm_kernel(const float* __restrict__ W_hh) {
    extern __shared__ float sm[];
    ull*   Wsm = (ull*)sm;                       // [kk*512 + row]
    float* g_s = sm + 16384;
    float* h_s = sm + 16384 + 512;
    float* c_s = sm + 16384 + 512 + 128;

    int tid = threadIdx.x;

    // register half: cols 0..95 as 24 x ulonglong2 (48 ull = 96 floats)
    ulonglong2 wr[24];
    const ulonglong2* wrow = (const ulonglong2*)(W_hh + (size_t)tid * 128);
#pragma unroll
    for (int i = 0; i < 24; i++) wr[i] = wrow[i];

    // smem half: cols 96..127 transposed
#pragma unroll
    for (int kk = 0; kk < 16; kk++) {
        Wsm[kk * 512 + tid] = *(const ull*)(W_hh + (size_t)tid * 128 + 96 + 2 * kk);
    }
    if (tid < 128) { h_s[tid] = 0.f; c_s[tid] = 0.f; }
    __syncthreads();

    float* leaf = g_hidden + (size_t)(Lc - 1) * Hc;
    float xg = g_xg[tid];

    for (int t = 0; t < Lc; t++) {
        float xg_n = 0.f;
        if (t + 1 < Lc) xg_n = g_xg[(size_t)(t + 1) * 512 + tid];

        ull acc0 = 0ull, acc1 = 0ull;
        const ulonglong2* h16 = (const ulonglong2*)h_s;
        // register half (h broadcast, LDS.128)
#pragma unroll
        for (int k = 0; k < 24; k++) {
            ulonglong2 hv = h16[k];
            fma2(acc0, wr[k].x, hv.x);
            fma2(acc1, wr[k].y, hv.y);
        }
        // smem half: cols 96..127 (16 ull h values at index 48..63)
        const ull* h2 = (const ull*)h_s;
#pragma unroll
        for (int kk = 0; kk < 16; kk++) {
            fma2(acc0, Wsm[kk * 512 + tid], h2[48 + kk]);
        }
        float2 s0 = unpk(acc0), s1 = unpk(acc1);
        g_s[tid] = xg + ((s0.x + s0.y) + (s1.x + s1.y));
        __syncthreads();
        if (tid < 128) {
            float ig = fast_sig(g_s[tid]);
            float fg = fast_sig(g_s[tid + 128]);
            float gg = fast_tanh(g_s[tid + 256]);
            float og = fast_sig(g_s[tid + 384]);
            float c = fg * c_s[tid] + ig * gg;
            c_s[tid] = c;
            float h = og * fast_tanh(c);
            h_s[tid] = h;
            leaf[(size_t)t * Hc + tid] = h;
        }
        __syncthreads();
        xg = xg_n;
    }
}

// ---------------- Stage C: bottom-up pair fusion (4 nodes/block) ----------
__global__ void p2h_kernel(const float* __restrict__ Wp, const float* __restrict__ bp,
                           int base, int count) {
    int n0 = base + blockIdx.x * 4;
    __shared__ float pair[4][256];
    int tid = threadIdx.x;  // 128
#pragma unroll
    for (int b = 0; b < 4; b++) {
        int node = n0 + b;
        if (node < base + count) {
            pair[b][tid]       = g_hidden[(size_t)(2 * node + 1) * Hc + tid];
            pair[b][tid + 128] = g_hidden[(size_t)(2 * node + 2) * Hc + tid];
        } else {
            pair[b][tid] = 0.f; pair[b][tid + 128] = 0.f;
        }
    }
    __syncthreads();
    float a0 = 0.f, a1 = 0.f, a2 = 0.f, a3 = 0.f;
    const float4* w = (const float4*)(Wp + (size_t)tid * 256);
    const float4* p0 = (const float4*)pair[0];
    const float4* p1 = (const float4*)pair[1];
    const float4* p2 = (const float4*)pair[2];
    const float4* p3 = (const float4*)pair[3];
#pragma unroll 8
    for (int k = 0; k < 64; k++) {
        float4 wv = __ldg(&w[k]);
        float4 v;
        v = p0[k]; a0 += wv.x * v.x + wv.y * v.y + wv.z * v.z + wv.w * v.w;
        v = p1[k]; a1 += wv.x * v.x + wv.y * v.y + wv.z * v.z + wv.w * v.w;
        v = p2[k]; a2 += wv.x * v.x + wv.y * v.y + wv.z * v.z + wv.w * v.w;
        v = p3[k]; a3 += wv.x * v.x + wv.y * v.y + wv.z * v.z + wv.w * v.w;
    }
    float bias = bp[tid];
    if (n0 + 0 < base + count) g_hidden[(size_t)(n0 + 0) * Hc + tid] = a0 + bias;
    if (n0 + 1 < base + count) g_hidden[(size_t)(n0 + 1) * Hc + tid] = a1 + bias;
    if (n0 + 2 < base + count) g_hidden[(size_t)(n0 + 2) * Hc + tid] = a2 + bias;
    if (n0 + 3 < base + count) g_hidden[(size_t)(n0 + 3) * Hc + tid] = a3 + bias;
}

// ---------------- Stage D: unary factors (+ v2f init, f2n root zero) ------
__global__ void unary_kernel(const float* __restrict__ W_uni, const float* __restrict__ b_uni) {
    int node = blockIdx.x;
    int t = threadIdx.x;  // 64
    __shared__ float hs[128];
    hs[t] = g_hidden[(size_t)node * Hc + t];
    hs[t + 64] = g_hidden[(size_t)node * Hc + 64 + t];
    __syncthreads();
    float acc = b_uni[t];
    const float4* w = (const float4*)(W_uni + (size_t)t * 128);
    const float4* h4 = (const float4*)hs;
#pragma unroll
    for (int k = 0; k < 32; k++) {
        float4 wv = __ldg(&w[k]);
        float4 hv = h4[k];
        acc += wv.x * hv.x + wv.y * hv.y + wv.z * hv.z + wv.w * hv.w;
    }
    g_unary[(size_t)node * Tc + t] = acc;
    g_v2f[(size_t)node * Tc + t] = acc;
    if (node == 0) g_f2n[t] = 0.f;
}

// ---------------- Stage E: edge factor GEMM (f32x2) -----------------------
// C[8190][4096] = P @ W_edge^T + b_edge; P rows built on the fly from g_hidden.
__global__ void __launch_bounds__(256) edge_gemm_kernel(const float* __restrict__ W,
                                                        const float* __restrict__ bias) {
    const int M = NEDGE;
    __shared__ float As[16][132];
    __shared__ float Bs[16][132];
    int m0 = blockIdx.y * 128;
    int n0 = blockIdx.x * 128;
    int tid = threadIdx.x;
    int tx = tid & 15, ty = tid >> 4;
    ull accp[8][4];
#pragma unroll
    for (int i = 0; i < 8; i++)
#pragma unroll
        for (int j = 0; j < 4; j++) accp[i][j] = 0ull;

    for (int k0 = 0; k0 < 256; k0 += 16) {
        // A tile: 128 edges x 16 k
#pragma unroll
        for (int i = 0; i < 2; i++) {
            int idx = tid + i * 256;
            int m = idx & 127, k4 = idx >> 7;
            int e = m0 + m;
            float4 v = make_float4(0.f, 0.f, 0.f, 0.f);
            if (e < M) {
                int kk = k0 + k4 * 4;
                int child = e + 1, parent = e >> 1;
                const float* src = (kk < 128)
                    ? g_hidden + (size_t)parent * Hc + kk
                    : g_hidden + (size_t)child * Hc + (kk - 128);
                v = *(const float4*)src;
            }
            As[k4 * 4 + 0][m] = v.x; As[k4 * 4 + 1][m] = v.y;
            As[k4 * 4 + 2][m] = v.z; As[k4 * 4 + 3][m] = v.w;
        }
        // B tile
#pragma unroll
        for (int i = 0; i < 2; i++) {
            int idx = tid + i * 256;
            int n = idx & 127, k4 = idx >> 7;
            float4 v = __ldg((const float4*)(W + (size_t)(n0 + n) * 256 + k0 + k4 * 4));
            Bs[k4 * 4 + 0][n] = v.x; Bs[k4 * 4 + 1][n] = v.y;
            Bs[k4 * 4 + 2][n] = v.z; Bs[k4 * 4 + 3][n] = v.w;
        }
        __syncthreads();
#pragma unroll
        for (int kk = 0; kk < 16; kk++) {
            float4 aA = *(const float4*)&As[kk][ty * 4];
            float4 aB = *(const float4*)&As[kk][64 + ty * 4];
            ulonglong2 b0 = *(const ulonglong2*)&Bs[kk][tx * 4];
            ulonglong2 b1 = *(const ulonglong2*)&Bs[kk][64 + tx * 4];
            ull b[4] = {b0.x, b0.y, b1.x, b1.y};
            float a[8] = {aA.x, aA.y, aA.z, aA.w, aB.x, aB.y, aB.z, aB.w};
#pragma unroll
            for (int i = 0; i < 8; i++) {
                ull as = splat2(a[i]);
#pragma unroll
                for (int j = 0; j < 4; j++) fma2(accp[i][j], as, b[j]);
            }
        }
        __syncthreads();
    }
    // store
#pragma unroll
    for (int hi = 0; hi < 2; hi++) {
#pragma unroll
        for (int i = 0; i < 4; i++) {
            int m = m0 + hi * 64 + ty * 4 + i;
            if (m < M) {
#pragma unroll
                for (int hj = 0; hj < 2; hj++) {
                    int n = n0 + hj * 64 + tx * 4;
                    float2 v0 = unpk(accp[hi * 4 + i][hj * 2 + 0]);
                    float2 v1 = unpk(accp[hi * 4 + i][hj * 2 + 1]);
                    float4 o = make_float4(v0.x + bias[n], v0.y + bias[n + 1],
                                           v1.x + bias[n + 2], v1.y + bias[n + 3]);
                    *(float4*)(g_edge + (size_t)m * 4096 + n) = o;
                }
            }
        }
    }
}

// ---------------- Stage F: upward pass (one level) ------------------------
__global__ void up_kernel(int base, int leafLevel, int hasParent) {
    int idx = base + blockIdx.x;
    int t = threadIdx.x;  // 64
    __shared__ float v[64];
    float val = g_v2f[(size_t)idx * Tc + t];
    if (!leafLevel) {
        val += g_f2p[(size_t)(2 * idx + 1) * Tc + t] + g_f2p[(size_t)(2 * idx + 2) * Tc + t];
        g_v2f[(size_t)idx * Tc + t] = val;
    }
    v[t] = val;
    __syncthreads();
    if (hasParent) {
        const float4* row = (const float4*)(g_edge + (size_t)(idx - 1) * 4096 + t * 64);
        float r[64];
#pragma unroll
        for (int c = 0; c < 16; c++) {
            float4 x = __ldg(row + c);
            r[4 * c] = x.x; r[4 * c + 1] = x.y; r[4 * c + 2] = x.z; r[4 * c + 3] = x.w;
        }
        float m = -3.4e38f;
#pragma unroll
        for (int c = 0; c < 64; c++) { r[c] += v[c]; m = fmaxf(m, r[c]); }
        float s = 0.f;
#pragma unroll
        for (int c = 0; c < 64; c++) s += __expf(r[c] - m);
        g_f2p[(size_t)idx * Tc + t] = m + __logf(s);
    }
}

// ---------------- Stage G: downward pass (one level) ----------------------
__global__ void down_kernel(int base) {
    int idx = base + blockIdx.x;
    int t = threadIdx.x;  // 64
    int par = (idx - 1) >> 1;
    int sib = (idx & 1) ? idx + 1 : idx - 1;
    __shared__ float p[64];
    p[t] = g_unary[(size_t)par * Tc + t] + g_f2n[(size_t)par * Tc + t]
         + g_f2p[(size_t)sib * Tc + t];
    __syncthreads();
    const float* e0 = g_edge + (size_t)(idx - 1) * 4096 + t;
    float r[64];
    float m = -3.4e38f;
#pragma unroll
    for (int tp = 0; tp < 64; tp++) {
        r[tp] = e0[(size_t)tp * 64] + p[tp];
        m = fmaxf(m, r[tp]);
    }
    float s = 0.f;
#pragma unroll
    for (int tp = 0; tp < 64; tp++) s += __expf(r[tp] - m);
    g_f2n[(size_t)idx * Tc + t] = m + __logf(s);
}

// ---------------- Stage H: beliefs + postorder scatter --------------------
__global__ void out_kernel(float* __restrict__ out) {
    int node = blockIdx.x;
    int t = threadIdx.x;  // 64
    int x = node + 1;
    int d = 31 - __clz(x);
    int start = 0, size = Nc;
    for (int b = d - 1; b >= 0; b--) {
        int half = (size - 1) >> 1;
        if ((x >> b) & 1) start += half;
        size = half;
    }
    int post = start + size - 1;
    out[(size_t)post * Tc + t] = g_v2f[(size_t)node * Tc + t] + g_f2n[(size_t)node * Tc + t];
}

// ---------------- launch ---------------------------------------------------
extern "C" void kernel_launch(void* const* d_in, const int* in_sizes, int n_in,
                              void* d_out, int out_size) {
    const int*   tokens = (const int*)d_in[0];
    const float* emb    = (const float*)d_in[1];
    const float* W_ih   = (const float*)d_in[2];
    const float* W_hh   = (const float*)d_in[3];
    const float* b_ih   = (const float*)d_in[4];
    const float* b_hh   = (const float*)d_in[5];
    const float* W_p2h  = (const float*)d_in[6];
    const float* b_p2h  = (const float*)d_in[7];
    const float* W_uni  = (const float*)d_in[8];
    const float* b_uni  = (const float*)d_in[9];
    const float* W_edge = (const float*)d_in[10];
    const float* b_edge = (const float*)d_in[11];
    float* out = (float*)d_out;

    static int smem_set = 0;
    if (!smem_set) {
        cudaFuncSetAttribute(lstm_kernel, cudaFuncAttributeMaxDynamicSharedMemorySize,
                             LSTM_SMEM_BYTES);
        smem_set = 1;
    }

    // A: embedding + input projection
    embed_gemm_kernel<<<Lc / 4, 128>>>(tokens, emb, W_ih, b_ih, b_hh);
    // B: sequential LSTM (weights fully on-chip, f32x2)
    lstm_kernel<<<1, 512, LSTM_SMEM_BYTES>>>(W_hh);
    // C: bottom-up fusion, levels D-1 .. 0
    for (int d = Dc - 1; d >= 0; d--) {
        int base = (1 << d) - 1;
        int count = 1 << d;
        p2h_kernel<<<(count + 3) / 4, 128>>>(W_p2h, b_p2h, base, count);
    }
    // D: unary factors
    unary_kernel<<<Nc, 64>>>(W_uni, b_uni);
    // E: edge factor GEMM
    {
        dim3 grid(4096 / 128, (NEDGE + 127) / 128);
        edge_gemm_kernel<<<grid, 256>>>(W_edge, b_edge);
    }
    // F: upward pass, levels D .. 0
    for (int d = Dc; d >= 0; d--) {
        int base = (1 << d) - 1;
        up_kernel<<<(1 << d), 64>>>(base, d == Dc ? 1 : 0, d > 0 ? 1 : 0);
    }
    // G: downward pass, levels 1 .. D
    for (int d = 1; d <= Dc; d++) {
        int base = (1 << d) - 1;
        down_kernel<<<(1 << d), 64>>>(base);
    }
    // H: beliefs in postorder
    out_kernel<<<Nc, 64>>>(out);
}

// round 5
// speedup vs baseline: 10.2930x; 1.3124x over previous
#include <cuda_runtime.h>
#include <cuda_bf16.h>
#include <math.h>
#include <stdint.h>

// Problem constants
#define Lc 4096
#define Ec 256
#define Hc 128
#define Tc 64
#define Dc 12
#define Nc 8191            // 2*L-1
#define NEDGE 8190         // N-1

typedef unsigned long long ull;

// ---------------- packed f32x2 helpers ------------------------------------
__device__ __forceinline__ void fma2(ull& d, ull a, ull b) {
    asm("fma.rn.f32x2 %0, %1, %2, %0;" : "+l"(d) : "l"(a), "l"(b));
}
__device__ __forceinline__ ull splat2(float a) {
    ull r; asm("mov.b64 %0, {%1, %1};" : "=l"(r) : "f"(a)); return r;
}
__device__ __forceinline__ float2 unpk(ull v) {
    float2 r; asm("mov.b64 {%0, %1}, %2;" : "=f"(r.x), "=f"(r.y) : "l"(v)); return r;
}

// ---------------- fast activations ----------------------------------------
__device__ __forceinline__ float fast_sig(float x) {
    float t;
    asm("ex2.approx.f32 %0, %1;" : "=f"(t) : "f"(-1.4426950408889634f * x));
    float r;
    asm("rcp.approx.f32 %0, %1;" : "=f"(r) : "f"(1.0f + t));
    return r;
}
__device__ __forceinline__ float fast_tanh(float x) {
    float r; asm("tanh.approx.f32 %0, %1;" : "=f"(r) : "f"(x)); return r;
}

// ---------------- scratch (device globals; no allocation) ----------------
__device__ float g_xg[Lc * 512];                 // W_ih@x + b_ih + b_hh   (8 MB)
__device__ float g_hidden[Nc * Hc];              // node hidden states
__device__ float g_unary[Nc * Tc];
__device__ float g_v2f[Nc * Tc];
__device__ float g_f2p[Nc * Tc];
__device__ float g_f2n[Nc * Tc];
__device__ float g_edge[(size_t)NEDGE * 4096];   // edge factors (134 MB)

// ---------------- Stage A: embedding + input projection -------------------
__global__ void embed_gemm_kernel(const int* __restrict__ tokens,
                                  const float* __restrict__ emb,
                                  const float* __restrict__ W_ih,
                                  const float* __restrict__ b_ih,
                                  const float* __restrict__ b_hh) {
    __shared__ float es[4][256];
    int t0 = blockIdx.x * 4;
    int tid = threadIdx.x;
    for (int i = tid; i < 4 * 256; i += 128) {
        int tl = i >> 8, k = i & 255;
        es[tl][k] = emb[(size_t)tokens[t0 + tl] * Ec + k];
    }
    __syncthreads();
    for (int r = 0; r < 4; r++) {
        int j = tid + 128 * r;
        float a0 = 0.f, a1 = 0.f, a2 = 0.f, a3 = 0.f;
        const float4* w4 = (const float4*)(W_ih + (size_t)j * 256);
        const float4* e0 = (const float4*)es[0];
        const float4* e1 = (const float4*)es[1];
        const float4* e2 = (const float4*)es[2];
        const float4* e3 = (const float4*)es[3];
#pragma unroll 8
        for (int k = 0; k < 64; k++) {
            float4 w = __ldg(&w4[k]);
            float4 v;
            v = e0[k]; a0 += w.x * v.x + w.y * v.y + w.z * v.z + w.w * v.w;
            v = e1[k]; a1 += w.x * v.x + w.y * v.y + w.z * v.z + w.w * v.w;
            v = e2[k]; a2 += w.x * v.x + w.y * v.y + w.z * v.z + w.w * v.w;
            v = e3[k]; a3 += w.x * v.x + w.y * v.y + w.z * v.z + w.w * v.w;
        }
        float bias = b_ih[j] + b_hh[j];
        g_xg[(size_t)(t0 + 0) * 512 + j] = a0 + bias;
        g_xg[(size_t)(t0 + 1) * 512 + j] = a1 + bias;
        g_xg[(size_t)(t0 + 2) * 512 + j] = a2 + bias;
        g_xg[(size_t)(t0 + 3) * 512 + j] = a3 + bias;
    }
}

// ---------------- Stage B: sequential LSTM (single CTA, 1024 thr) ---------
// All of W_hh lives in registers: each thread owns half a gate row (64 cols
// = 16 ull). Lanes 0-15 of a warp: rows w*16+l, cols 0-63 (read h from hA);
// lanes 16-31: same rows, cols 64-127 (read h from bank-skewed copy hB).
// Pair-reduce with shfl.xor(16).
// smem float layout (static):
//   [0,512)    g_s
//   [512,640)  hA
//   [640,768)  c_s
//   [772,900)  hB (skewed: base ≡ 4 mod 32 banks)
__global__ void __launch_bounds__(1024, 1) lstm_kernel(const float* __restrict__ W_hh) {
    __shared__ __align__(16) float sm[904];
    float* g_s = sm;
    float* hA  = sm + 512;
    float* c_s = sm + 640;
    float* hB  = sm + 772;

    int tid  = threadIdx.x;
    int w    = tid >> 5;
    int lane = tid & 31;
    int half = lane >> 4;               // 0: cols 0-63, 1: cols 64-127
    int row  = w * 16 + (lane & 15);    // gate row 0..511

    // weights: 16 ull = 64 floats
    ull wr[16];
    const ull* wsrc = (const ull*)(W_hh + (size_t)row * 128 + half * 64);
#pragma unroll
    for (int i = 0; i < 16; i++) wr[i] = wsrc[i];

    if (tid < 128) { hA[tid] = 0.f; hB[tid] = 0.f; c_s[tid] = 0.f; }
    __syncthreads();

    // per-lane h pointer: half 0 reads hA[0..64), half 1 reads hB[64..128)
    const ulonglong2* hp = half ? (const ulonglong2*)(hB + 64)
                                : (const ulonglong2*)hA;

    float* leaf = g_hidden + (size_t)(Lc - 1) * Hc;
    float xg = g_xg[row];

    for (int t = 0; t < Lc; t++) {
        float xg_n = 0.f;
        if (t + 1 < Lc) xg_n = g_xg[(size_t)(t + 1) * 512 + row];

        ull acc0 = 0ull, acc1 = 0ull;
#pragma unroll
        for (int k = 0; k < 8; k++) {
            ulonglong2 hv = hp[k];
            fma2(acc0, wr[2 * k],     hv.x);
            fma2(acc1, wr[2 * k + 1], hv.y);
        }
        float2 s0 = unpk(acc0), s1 = unpk(acc1);
        float partial = (s0.x + s0.y) + (s1.x + s1.y);
        float other = __shfl_xor_sync(0xffffffffu, partial, 16);
        if (half == 0) g_s[row] = partial + other + xg;
        __syncthreads();
        if (tid < 128) {
            float ig = fast_sig(g_s[tid]);
            float fg = fast_sig(g_s[tid + 128]);
            float gg = fast_tanh(g_s[tid + 256]);
            float og = fast_sig(g_s[tid + 384]);
            float c = fg * c_s[tid] + ig * gg;
            c_s[tid] = c;
            float h = og * fast_tanh(c);
            hA[tid] = h;
            hB[tid] = h;
            leaf[(size_t)t * Hc + tid] = h;
        }
        __syncthreads();
        xg = xg_n;
    }
}

// ---------------- Stage C: bottom-up pair fusion (8 nodes/block) ----------
__global__ void p2h_kernel(const float* __restrict__ Wp, const float* __restrict__ bp,
                           int base, int count) {
    int n0 = base + blockIdx.x * 8;
    __shared__ float pair[8][256];
    int tid = threadIdx.x;  // 128
#pragma unroll
    for (int b = 0; b < 8; b++) {
        int node = n0 + b;
        if (node < base + count) {
            pair[b][tid]       = g_hidden[(size_t)(2 * node + 1) * Hc + tid];
            pair[b][tid + 128] = g_hidden[(size_t)(2 * node + 2) * Hc + tid];
        } else {
            pair[b][tid] = 0.f; pair[b][tid + 128] = 0.f;
        }
    }
    __syncthreads();
    float a[8] = {};
    const float4* wv4 = (const float4*)(Wp + (size_t)tid * 256);
#pragma unroll 4
    for (int k = 0; k < 64; k++) {
        float4 wv = __ldg(&wv4[k]);
#pragma unroll
        for (int b = 0; b < 8; b++) {
            float4 v = ((const float4*)pair[b])[k];
            a[b] += wv.x * v.x + wv.y * v.y + wv.z * v.z + wv.w * v.w;
        }
    }
    float bias = bp[tid];
#pragma unroll
    for (int b = 0; b < 8; b++) {
        int node = n0 + b;
        if (node < base + count)
            g_hidden[(size_t)node * Hc + tid] = a[b] + bias;
    }
}

// ---------------- Stage D: unary factors (+ v2f init, f2n root zero) ------
__global__ void unary_kernel(const float* __restrict__ W_uni, const float* __restrict__ b_uni) {
    int node = blockIdx.x;
    int t = threadIdx.x;  // 64
    __shared__ float hs[128];
    hs[t] = g_hidden[(size_t)node * Hc + t];
    hs[t + 64] = g_hidden[(size_t)node * Hc + 64 + t];
    __syncthreads();
    float acc = b_uni[t];
    const float4* w = (const float4*)(W_uni + (size_t)t * 128);
    const float4* h4 = (const float4*)hs;
#pragma unroll
    for (int k = 0; k < 32; k++) {
        float4 wv = __ldg(&w[k]);
        float4 hv = h4[k];
        acc += wv.x * hv.x + wv.y * hv.y + wv.z * hv.z + wv.w * hv.w;
    }
    g_unary[(size_t)node * Tc + t] = acc;
    g_v2f[(size_t)node * Tc + t] = acc;
    if (node == 0) g_f2n[t] = 0.f;
}

// ---------------- Stage E: edge factor GEMM (f32x2) -----------------------
__global__ void __launch_bounds__(256) edge_gemm_kernel(const float* __restrict__ W,
                                                        const float* __restrict__ bias) {
    const int M = NEDGE;
    __shared__ float As[16][132];
    __shared__ float Bs[16][132];
    int m0 = blockIdx.y * 128;
    int n0 = blockIdx.x * 128;
    int tid = threadIdx.x;
    int tx = tid & 15, ty = tid >> 4;
    ull accp[8][4];
#pragma unroll
    for (int i = 0; i < 8; i++)
#pragma unroll
        for (int j = 0; j < 4; j++) accp[i][j] = 0ull;

    for (int k0 = 0; k0 < 256; k0 += 16) {
#pragma unroll
        for (int i = 0; i < 2; i++) {
            int idx = tid + i * 256;
            int m = idx & 127, k4 = idx >> 7;
            int e = m0 + m;
            float4 v = make_float4(0.f, 0.f, 0.f, 0.f);
            if (e < M) {
                int kk = k0 + k4 * 4;
                int child = e + 1, parent = e >> 1;
                const float* src = (kk < 128)
                    ? g_hidden + (size_t)parent * Hc + kk
                    : g_hidden + (size_t)child * Hc + (kk - 128);
                v = *(const float4*)src;
            }
            As[k4 * 4 + 0][m] = v.x; As[k4 * 4 + 1][m] = v.y;
            As[k4 * 4 + 2][m] = v.z; As[k4 * 4 + 3][m] = v.w;
        }
#pragma unroll
        for (int i = 0; i < 2; i++) {
            int idx = tid + i * 256;
            int n = idx & 127, k4 = idx >> 7;
            float4 v = __ldg((const float4*)(W + (size_t)(n0 + n) * 256 + k0 + k4 * 4));
            Bs[k4 * 4 + 0][n] = v.x; Bs[k4 * 4 + 1][n] = v.y;
            Bs[k4 * 4 + 2][n] = v.z; Bs[k4 * 4 + 3][n] = v.w;
        }
        __syncthreads();
#pragma unroll
        for (int kk = 0; kk < 16; kk++) {
            float4 aA = *(const float4*)&As[kk][ty * 4];
            float4 aB = *(const float4*)&As[kk][64 + ty * 4];
            ulonglong2 b0 = *(const ulonglong2*)&Bs[kk][tx * 4];
            ulonglong2 b1 = *(const ulonglong2*)&Bs[kk][64 + tx * 4];
            ull b[4] = {b0.x, b0.y, b1.x, b1.y};
            float a[8] = {aA.x, aA.y, aA.z, aA.w, aB.x, aB.y, aB.z, aB.w};
#pragma unroll
            for (int i = 0; i < 8; i++) {
                ull as = splat2(a[i]);
#pragma unroll
                for (int j = 0; j < 4; j++) fma2(accp[i][j], as, b[j]);
            }
        }
        __syncthreads();
    }
#pragma unroll
    for (int hi = 0; hi < 2; hi++) {
#pragma unroll
        for (int i = 0; i < 4; i++) {
            int m = m0 + hi * 64 + ty * 4 + i;
            if (m < M) {
#pragma unroll
                for (int hj = 0; hj < 2; hj++) {
                    int n = n0 + hj * 64 + tx * 4;
                    float2 v0 = unpk(accp[hi * 4 + i][hj * 2 + 0]);
                    float2 v1 = unpk(accp[hi * 4 + i][hj * 2 + 1]);
                    float4 o = make_float4(v0.x + bias[n], v0.y + bias[n + 1],
                                           v1.x + bias[n + 2], v1.y + bias[n + 3]);
                    *(float4*)(g_edge + (size_t)m * 4096 + n) = o;
                }
            }
        }
    }
}

// ---------------- Stage F: upward pass (one level) ------------------------
__global__ void up_kernel(int base, int leafLevel, int hasParent) {
    int idx = base + blockIdx.x;
    int t = threadIdx.x;  // 64
    __shared__ float v[64];
    float val = g_v2f[(size_t)idx * Tc + t];
    if (!leafLevel) {
        val += g_f2p[(size_t)(2 * idx + 1) * Tc + t] + g_f2p[(size_t)(2 * idx + 2) * Tc + t];
        g_v2f[(size_t)idx * Tc + t] = val;
    }
    v[t] = val;
    __syncthreads();
    if (hasParent) {
        const float4* row = (const float4*)(g_edge + (size_t)(idx - 1) * 4096 + t * 64);
        float r[64];
#pragma unroll
        for (int c = 0; c < 16; c++) {
            float4 x = __ldg(row + c);
            r[4 * c] = x.x; r[4 * c + 1] = x.y; r[4 * c + 2] = x.z; r[4 * c + 3] = x.w;
        }
        float m = -3.4e38f;
#pragma unroll
        for (int c = 0; c < 64; c++) { r[c] += v[c]; m = fmaxf(m, r[c]); }
        float s = 0.f;
#pragma unroll
        for (int c = 0; c < 64; c++) s += __expf(r[c] - m);
        g_f2p[(size_t)idx * Tc + t] = m + __logf(s);
    }
}

// ---------------- Stage G: downward pass (one level) ----------------------
__global__ void down_kernel(int base) {
    int idx = base + blockIdx.x;
    int t = threadIdx.x;  // 64
    int par = (idx - 1) >> 1;
    int sib = (idx & 1) ? idx + 1 : idx - 1;
    __shared__ float p[64];
    p[t] = g_unary[(size_t)par * Tc + t] + g_f2n[(size_t)par * Tc + t]
         + g_f2p[(size_t)sib * Tc + t];
    __syncthreads();
    const float* e0 = g_edge + (size_t)(idx - 1) * 4096 + t;
    float r[64];
    float m = -3.4e38f;
#pragma unroll
    for (int tp = 0; tp < 64; tp++) {
        r[tp] = e0[(size_t)tp * 64] + p[tp];
        m = fmaxf(m, r[tp]);
    }
    float s = 0.f;
#pragma unroll
    for (int tp = 0; tp < 64; tp++) s += __expf(r[tp] - m);
    g_f2n[(size_t)idx * Tc + t] = m + __logf(s);
}

// ---------------- Stage H: beliefs + postorder scatter --------------------
__global__ void out_kernel(float* __restrict__ out) {
    int node = blockIdx.x;
    int t = threadIdx.x;  // 64
    int x = node + 1;
    int d = 31 - __clz(x);
    int start = 0, size = Nc;
    for (int b = d - 1; b >= 0; b--) {
        int half = (size - 1) >> 1;
        if ((x >> b) & 1) start += half;
        size = half;
    }
    int post = start + size - 1;
    out[(size_t)post * Tc + t] = g_v2f[(size_t)node * Tc + t] + g_f2n[(size_t)node * Tc + t];
}

// ---------------- launch ---------------------------------------------------
extern "C" void kernel_launch(void* const* d_in, const int* in_sizes, int n_in,
                              void* d_out, int out_size) {
    const int*   tokens = (const int*)d_in[0];
    const float* emb    = (const float*)d_in[1];
    const float* W_ih   = (const float*)d_in[2];
    const float* W_hh   = (const float*)d_in[3];
    const float* b_ih   = (const float*)d_in[4];
    const float* b_hh   = (const float*)d_in[5];
    const float* W_p2h  = (const float*)d_in[6];
    const float* b_p2h  = (const float*)d_in[7];
    const float* W_uni  = (const float*)d_in[8];
    const float* b_uni  = (const float*)d_in[9];
    const float* W_edge = (const float*)d_in[10];
    const float* b_edge = (const float*)d_in[11];
    float* out = (float*)d_out;

    // A: embedding + input projection
    embed_gemm_kernel<<<Lc / 4, 128>>>(tokens, emb, W_ih, b_ih, b_hh);
    // B: sequential LSTM (all weights in registers)
    lstm_kernel<<<1, 1024>>>(W_hh);
    // C: bottom-up fusion, levels D-1 .. 0
    for (int d = Dc - 1; d >= 0; d--) {
        int base = (1 << d) - 1;
        int count = 1 << d;
        p2h_kernel<<<(count + 7) / 8, 128>>>(W_p2h, b_p2h, base, count);
    }
    // D: unary factors
    unary_kernel<<<Nc, 64>>>(W_uni, b_uni);
    // E: edge factor GEMM
    {
        dim3 grid(4096 / 128, (NEDGE + 127) / 128);
        edge_gemm_kernel<<<grid, 256>>>(W_edge, b_edge);
    }
    // F: upward pass, levels D .. 0
    for (int d = Dc; d >= 0; d--) {
        int base = (1 << d) - 1;
        up_kernel<<<(1 << d), 64>>>(base, d == Dc ? 1 : 0, d > 0 ? 1 : 0);
    }
    // G: downward pass, levels 1 .. D
    for (int d = 1; d <= Dc; d++) {
        int base = (1 << d) - 1;
        down_kernel<<<(1 << d), 64>>>(base);
    }
    // H: beliefs in postorder
    out_kernel<<<Nc, 64>>>(out);
}